// round 7
// baseline (speedup 1.0000x reference)
#include <cuda_runtime.h>
#include <cuda_bf16.h>

// LandmarksLoss: mean((pred - true)^2), true = windowed 128x128 bell table.
// Grid = n_bl * 7 CTAs; each CTA owns 32 rows (1792 float4 = 7 iters x 256 thr)
// of one image -> perfectly uniform work units, sub-us CTA duration so HW
// work-stealing kills wave imbalance. 7 front-batched float4 loads per thread
// (MLP=7). Deterministic last-block final reduction.

#define H_DIM    224
#define W_DIM    224
#define ROWF4    (W_DIM / 4)           // 56 float4 per row
#define NF4_IMG  (H_DIM * ROWF4)       // 12544 float4 per image
#define SEGS     7                     // CTAs per image
#define SEG_ROWS (H_DIM / SEGS)        // 32 rows per CTA
#define SEG_F4   (SEG_ROWS * ROWF4)    // 1792 float4 per CTA
#define THREADS  256
#define ITERS    (SEG_F4 / THREADS)    // 7
#define NWARP    (THREADS / 32)
#define MAX_PART 32768
#define DELTA    128
#define HALF     64

__device__ float        g_partials[MAX_PART];
__device__ unsigned int g_count = 0;

__device__ __forceinline__ float blockReduce(float v, float* s)
{
    #pragma unroll
    for (int off = 16; off > 0; off >>= 1)
        v += __shfl_down_sync(0xFFFFFFFFu, v, off);
    const int lane = threadIdx.x & 31;
    const int wid  = threadIdx.x >> 5;
    if (lane == 0) s[wid] = v;
    __syncthreads();
    if (wid == 0) {
        v = (lane < NWARP) ? s[lane] : 0.0f;
        #pragma unroll
        for (int off = NWARP / 2; off > 0; off >>= 1)
            v += __shfl_down_sync(0xFFFFFFFFu, v, off);
    }
    return v;  // valid in thread 0
}

__global__ void __launch_bounds__(THREADS)
landmarks_fused(const float* __restrict__ pred,
                const float* __restrict__ lm,
                const float* __restrict__ bell,
                float* __restrict__ out,
                int n_part, float inv_n)
{
    const int bl  = blockIdx.x / SEGS;
    const int seg = blockIdx.x % SEGS;

    const float4* img4 = reinterpret_cast<const float4*>(pred)
                       + (size_t)bl * NF4_IMG + seg * SEG_F4 + threadIdx.x;

    // landmarks: [...,0] = y_r (cols), [...,1] = x_r (rows); jnp.round = rintf
    const int yr = (int)rintf(__ldg(&lm[2 * bl + 0]));
    const int xr = (int)rintf(__ldg(&lm[2 * bl + 1]));
    const int xoff = HALF - xr + seg * SEG_ROWS;  // ix = local_row + xoff
    const int yoff = HALF - yr;                   // iy = w + yoff

    // Front-batch all 7 float4 loads (independent of bell/landmark math).
    float4 p[ITERS];
    #pragma unroll
    for (int k = 0; k < ITERS; ++k)
        p[k] = __ldg(img4 + k * THREADS);

    float acc = 0.0f;

    #pragma unroll
    for (int k = 0; k < ITERS; ++k) {
        const int local = threadIdx.x + k * THREADS;   // 0..1791
        const int hl    = local / ROWF4;               // local row 0..31
        const int w4    = local - hl * ROWF4;          // float4 col 0..55

        const int ix  = hl + xoff;
        const int iy0 = 4 * w4 + yoff;
        const bool rowok = ((unsigned)ix < (unsigned)DELTA);
        const float* brow = bell + (ix << 7);

        float t0 = 0.f, t1 = 0.f, t2 = 0.f, t3 = 0.f;
        if (rowok & ((unsigned)(iy0 + 0) < (unsigned)DELTA)) t0 = __ldg(&brow[iy0 + 0]);
        if (rowok & ((unsigned)(iy0 + 1) < (unsigned)DELTA)) t1 = __ldg(&brow[iy0 + 1]);
        if (rowok & ((unsigned)(iy0 + 2) < (unsigned)DELTA)) t2 = __ldg(&brow[iy0 + 2]);
        if (rowok & ((unsigned)(iy0 + 3) < (unsigned)DELTA)) t3 = __ldg(&brow[iy0 + 3]);

        float d;
        d = p[k].x - t0; acc = fmaf(d, d, acc);
        d = p[k].y - t1; acc = fmaf(d, d, acc);
        d = p[k].z - t2; acc = fmaf(d, d, acc);
        d = p[k].w - t3; acc = fmaf(d, d, acc);
    }

    __shared__ float s[NWARP];
    const float bsum = blockReduce(acc, s);

    __shared__ bool amLast;
    if (threadIdx.x == 0) {
        g_partials[blockIdx.x] = bsum;
        __threadfence();
        const unsigned prev = atomicAdd(&g_count, 1u);
        amLast = (prev == (unsigned)(gridDim.x - 1));
    }
    __syncthreads();

    if (amLast) {
        // Deterministic final reduction: fixed index order every run.
        float tot = 0.0f;
        for (int i = threadIdx.x; i < n_part; i += THREADS)
            tot += __ldcg(&g_partials[i]);
        __syncthreads();   // reuse s[] safely
        const float t = blockReduce(tot, s);
        if (threadIdx.x == 0) {
            out[0] = t * inv_n;
            g_count = 0;   // reset for next graph replay
        }
    }
}

extern "C" void kernel_launch(void* const* d_in, const int* in_sizes, int n_in,
                              void* d_out, int out_size)
{
    const float* pred = (const float*)d_in[0];  // (B, L, 224, 224)
    const float* lm   = (const float*)d_in[1];  // (B, L, 2)
    const float* bell = (const float*)d_in[2];  // (128, 128)
    float* out = (float*)d_out;

    const int n_bl  = in_sizes[1] / 2;          // B*L = 1088
    const int gridx = n_bl * SEGS;              // 7616 CTAs
    const float inv_n = 1.0f / ((float)n_bl * (float)(H_DIM * W_DIM));

    landmarks_fused<<<gridx, THREADS>>>(pred, lm, bell, out, gridx, inv_n);
}